// round 3
// baseline (speedup 1.0000x reference)
#include <cuda_runtime.h>
#include <mma.h>
#include <math.h>

using namespace nvcuda;

// Problem dims
constexpr int  Bb = 2, Nn = 2048, Cc_ = 1024, Hh = 16, Dd = 64, Ff = 4096;
constexpr int  MR = Bb * Nn;                 // 4096 token rows
constexpr size_t SZ4M = (size_t)MR * Cc_;    // 4096*1024 = 4M floats

// Scratch layout (floats)
constexpr size_t OFF_H   = 0;
constexpr size_t OFF_QL  = OFF_H   + SZ4M;
constexpr size_t OFF_KL  = OFF_QL  + SZ4M;
constexpr size_t OFF_VL  = OFF_KL  + SZ4M;
constexpr size_t OFF_QR  = OFF_VL  + SZ4M;
constexpr size_t OFF_KR  = OFF_QR  + SZ4M;
constexpr size_t OFF_VT  = OFF_KR  + SZ4M;
constexpr size_t OFF_S   = OFF_VT  + SZ4M;                      // scores: 32*2048*2048
constexpr size_t SZ_S    = (size_t)Bb * Hh * Nn * Nn;           // 128M floats
constexpr size_t OFF_AO  = OFF_S   + SZ_S;
constexpr size_t OFF_AOT = OFF_AO  + SZ4M;
constexpr size_t OFF_X1  = OFF_AOT + SZ4M;
constexpr size_t OFF_H2  = OFF_X1  + SZ4M;
constexpr size_t OFF_G1  = OFF_H2  + SZ4M;
constexpr size_t SZ_G1   = (size_t)MR * Ff;                     // 16M floats
constexpr size_t SCRATCH_FLOATS = OFF_G1 + SZ_G1;               // 188M floats (~752MB)

__device__ float g_scratch[SCRATCH_FLOATS];

// ---------------------------------------------------------------------------
// LayerNorm: one block per row, C=1024, 256 threads x 4 elems
// ---------------------------------------------------------------------------
__global__ __launch_bounds__(256) void ln_kernel(const float* __restrict__ x,
                                                 const float* __restrict__ g,
                                                 const float* __restrict__ b,
                                                 float* __restrict__ out)
{
    const int row = blockIdx.x;
    const int t = threadIdx.x;
    const float* xr = x + (size_t)row * Cc_;

    float4 v = *reinterpret_cast<const float4*>(xr + t * 4);
    float s  = v.x + v.y + v.z + v.w;
    float ss = v.x * v.x + v.y * v.y + v.z * v.z + v.w * v.w;

    // warp reduce
    #pragma unroll
    for (int o = 16; o > 0; o >>= 1) {
        s  += __shfl_xor_sync(0xffffffff, s,  o);
        ss += __shfl_xor_sync(0xffffffff, ss, o);
    }
    __shared__ float red0[8], red1[8];
    int w = t >> 5;
    if ((t & 31) == 0) { red0[w] = s; red1[w] = ss; }
    __syncthreads();
    float st = 0.f, sst = 0.f;
    #pragma unroll
    for (int i = 0; i < 8; i++) { st += red0[i]; sst += red1[i]; }

    const float mean = st * (1.0f / Cc_);
    const float var  = sst * (1.0f / Cc_) - mean * mean;
    const float inv  = rsqrtf(var + 1e-6f);

    float4 gv = *reinterpret_cast<const float4*>(g + t * 4);
    float4 bv = *reinterpret_cast<const float4*>(b + t * 4);
    float4 o4;
    o4.x = (v.x - mean) * inv * gv.x + bv.x;
    o4.y = (v.y - mean) * inv * gv.y + bv.y;
    o4.z = (v.z - mean) * inv * gv.z + bv.z;
    o4.w = (v.w - mean) * inv * gv.w + bv.w;
    *reinterpret_cast<float4*>(out + (size_t)row * Cc_ + t * 4) = o4;
}

// ---------------------------------------------------------------------------
// RoPE + head transpose: [B,N,H,D] -> [B,H,N,D], v plain transpose
// ---------------------------------------------------------------------------
__global__ __launch_bounds__(256) void rope_kernel(const float* __restrict__ ql,
                                                   const float* __restrict__ kl,
                                                   const float* __restrict__ vl,
                                                   const float* __restrict__ cosT,
                                                   const float* __restrict__ sinT,
                                                   float* __restrict__ qr,
                                                   float* __restrict__ kr,
                                                   float* __restrict__ vt)
{
    int idx = blockIdx.x * blockDim.x + threadIdx.x;   // over B*H*N*D = 4M
    if (idx >= Bb * Hh * Nn * Dd) return;
    const int d = idx & 63;
    const int n = (idx >> 6) & 2047;
    const int h = (idx >> 17) & 15;
    const int bidx = idx >> 21;
    const size_t inBase = ((size_t)(bidx * Nn + n)) * Cc_ + h * Dd;
    const float c = cosT[n * Dd + d];
    const float s = sinT[n * Dd + d];
    const float qv = ql[inBase + d];
    const float kv = kl[inBase + d];
    float qp, kp;
    if (d < 32) { qp = -ql[inBase + d + 32]; kp = -kl[inBase + d + 32]; }
    else        { qp =  ql[inBase + d - 32]; kp =  kl[inBase + d - 32]; }
    qr[idx] = qv * c + qp * s;
    kr[idx] = kv * c + kp * s;
    vt[idx] = vl[inBase + d];
}

// ---------------------------------------------------------------------------
// Softmax over rows of length 2048, one block per row
// ---------------------------------------------------------------------------
__global__ __launch_bounds__(256) void softmax_kernel(float* __restrict__ S)
{
    const size_t row = blockIdx.x;
    float* p = S + row * (size_t)Nn;
    const int t = threadIdx.x;

    float4 v0 = *reinterpret_cast<const float4*>(p + t * 4);
    float4 v1 = *reinterpret_cast<const float4*>(p + 1024 + t * 4);

    float m = fmaxf(fmaxf(fmaxf(v0.x, v0.y), fmaxf(v0.z, v0.w)),
                    fmaxf(fmaxf(v1.x, v1.y), fmaxf(v1.z, v1.w)));
    #pragma unroll
    for (int o = 16; o > 0; o >>= 1) m = fmaxf(m, __shfl_xor_sync(0xffffffff, m, o));
    __shared__ float red[8];
    int w = t >> 5;
    if ((t & 31) == 0) red[w] = m;
    __syncthreads();
    float mx = red[0];
    #pragma unroll
    for (int i = 1; i < 8; i++) mx = fmaxf(mx, red[i]);
    __syncthreads();

    v0.x = expf(v0.x - mx); v0.y = expf(v0.y - mx); v0.z = expf(v0.z - mx); v0.w = expf(v0.w - mx);
    v1.x = expf(v1.x - mx); v1.y = expf(v1.y - mx); v1.z = expf(v1.z - mx); v1.w = expf(v1.w - mx);
    float s = v0.x + v0.y + v0.z + v0.w + v1.x + v1.y + v1.z + v1.w;
    #pragma unroll
    for (int o = 16; o > 0; o >>= 1) s += __shfl_xor_sync(0xffffffff, s, o);
    if ((t & 31) == 0) red[w] = s;
    __syncthreads();
    float st = 0.f;
    #pragma unroll
    for (int i = 0; i < 8; i++) st += red[i];
    const float inv = 1.0f / st;

    v0.x *= inv; v0.y *= inv; v0.z *= inv; v0.w *= inv;
    v1.x *= inv; v1.y *= inv; v1.z *= inv; v1.w *= inv;
    *reinterpret_cast<float4*>(p + t * 4)        = v0;
    *reinterpret_cast<float4*>(p + 1024 + t * 4) = v1;
}

// ---------------------------------------------------------------------------
// [B,H,N,D] -> [B,N,H*D]
// ---------------------------------------------------------------------------
__global__ __launch_bounds__(256) void unpermute_kernel(const float* __restrict__ ao,
                                                        float* __restrict__ aot)
{
    int idx = blockIdx.x * blockDim.x + threadIdx.x;   // over B*N*C = 4M
    if (idx >= Bb * Nn * Cc_) return;
    const int c = idx & 1023;
    const int n = (idx >> 10) & 2047;
    const int bidx = idx >> 21;
    const int h = c >> 6;
    const int d = c & 63;
    aot[idx] = ao[(((size_t)(bidx * Hh + h) * Nn) + n) * Dd + d];
}

// ---------------------------------------------------------------------------
// Generic batched GEMM (wmma tf32):
//   C[M,N] = alpha * A[M,K] * op(B)  (+bias)(gelu)(+resid)
//   transB=1: B is W[N,K] row-major (C = A*W^T);  transB=0: B is [K,N] row-major
// 128x128 block tile, K-tile 32, 8 warps (4Mx2N), 32x64 warp tile.
// ---------------------------------------------------------------------------
__global__ __launch_bounds__(256) void gemm_tf32(const float* __restrict__ A,
                                                 const float* __restrict__ Bm,
                                                 float* __restrict__ Co,
                                                 const float* __restrict__ bias,
                                                 const float* __restrict__ resid,
                                                 int M, int N, int K,
                                                 size_t strideA, size_t strideB, size_t strideC,
                                                 float alpha, int transB, int gelu)
{
    __shared__ float As[128][36];
    __shared__ float Bs[128][36];
    __shared__ float epi[8][16 * 20];

    const int tid = threadIdx.x;
    const int bz = blockIdx.z;
    const int rowBase = blockIdx.y * 128;
    const int colBase = blockIdx.x * 128;
    A  += (size_t)bz * strideA;
    Bm += (size_t)bz * strideB;
    Co += (size_t)bz * strideC;

    wmma::fragment<wmma::accumulator, 16, 16, 8, float> acc[2][4];
    #pragma unroll
    for (int i = 0; i < 2; i++)
        #pragma unroll
        for (int j = 0; j < 4; j++) wmma::fill_fragment(acc[i][j], 0.0f);

    const int warpId = tid >> 5;
    const int warpM = warpId & 3;   // 0..3
    const int warpN = warpId >> 2;  // 0..1

    const int kTiles = K >> 5;
    for (int kt = 0; kt < kTiles; ++kt) {
        // Load A tile (128 x 32)
        #pragma unroll
        for (int i = 0; i < 4; i++) {
            int v = tid + i * 256;        // 0..1023
            int r = v >> 3;               // 0..127
            int c4 = (v & 7) << 2;        // 0..28
            int gr = rowBase + r;
            float4 val = make_float4(0.f, 0.f, 0.f, 0.f);
            if (gr < M)
                val = *reinterpret_cast<const float4*>(A + (size_t)gr * K + (kt << 5) + c4);
            As[r][c4 + 0] = wmma::__float_to_tf32(val.x);
            As[r][c4 + 1] = wmma::__float_to_tf32(val.y);
            As[r][c4 + 2] = wmma::__float_to_tf32(val.z);
            As[r][c4 + 3] = wmma::__float_to_tf32(val.w);
        }
        // Load B tile into Bs[n][k] (128 x 32)
        if (transB) {
            #pragma unroll
            for (int i = 0; i < 4; i++) {
                int v = tid + i * 256;
                int r = v >> 3;           // n within tile
                int c4 = (v & 7) << 2;    // k within tile
                int gn = colBase + r;
                float4 val = make_float4(0.f, 0.f, 0.f, 0.f);
                if (gn < N)
                    val = *reinterpret_cast<const float4*>(Bm + (size_t)gn * K + (kt << 5) + c4);
                Bs[r][c4 + 0] = wmma::__float_to_tf32(val.x);
                Bs[r][c4 + 1] = wmma::__float_to_tf32(val.y);
                Bs[r][c4 + 2] = wmma::__float_to_tf32(val.z);
                Bs[r][c4 + 3] = wmma::__float_to_tf32(val.w);
            }
        } else {
            #pragma unroll
            for (int i = 0; i < 4; i++) {
                int v = tid + i * 256;    // 0..1023
                int kk = v >> 5;          // 0..31
                int n4 = (v & 31) << 2;   // 0..124
                int gn = colBase + n4;
                float4 val = make_float4(0.f, 0.f, 0.f, 0.f);
                if (gn + 3 < N)
                    val = *reinterpret_cast<const float4*>(Bm + (size_t)((kt << 5) + kk) * N + gn);
                Bs[n4 + 0][kk] = wmma::__float_to_tf32(val.x);
                Bs[n4 + 1][kk] = wmma::__float_to_tf32(val.y);
                Bs[n4 + 2][kk] = wmma::__float_to_tf32(val.z);
                Bs[n4 + 3][kk] = wmma::__float_to_tf32(val.w);
            }
        }
        __syncthreads();

        #pragma unroll
        for (int kk = 0; kk < 32; kk += 8) {
            wmma::fragment<wmma::matrix_a, 16, 16, 8, wmma::precision::tf32, wmma::row_major> af[2];
            wmma::fragment<wmma::matrix_b, 16, 16, 8, wmma::precision::tf32, wmma::col_major> bf[4];
            #pragma unroll
            for (int i = 0; i < 2; i++)
                wmma::load_matrix_sync(af[i], &As[warpM * 32 + i * 16][kk], 36);
            #pragma unroll
            for (int j = 0; j < 4; j++)
                wmma::load_matrix_sync(bf[j], &Bs[warpN * 64 + j * 16][kk], 36);
            #pragma unroll
            for (int i = 0; i < 2; i++)
                #pragma unroll
                for (int j = 0; j < 4; j++)
                    wmma::mma_sync(acc[i][j], af[i], bf[j], acc[i][j]);
        }
        __syncthreads();
    }

    // Epilogue through per-warp smem patch
    float* patch = epi[warpId];
    const int lane = tid & 31;
    #pragma unroll
    for (int i = 0; i < 2; i++) {
        #pragma unroll
        for (int j = 0; j < 4; j++) {
            wmma::store_matrix_sync(patch, acc[i][j], 20, wmma::mem_row_major);
            __syncwarp();
            #pragma unroll
            for (int e = lane; e < 256; e += 32) {
                int r = e >> 4, c = e & 15;
                int gr = rowBase + warpM * 32 + i * 16 + r;
                int gc = colBase + warpN * 64 + j * 16 + c;
                if (gr < M && gc < N) {
                    float vv = patch[r * 20 + c] * alpha;
                    if (bias)  vv += bias[gc];
                    if (gelu)  vv = 0.5f * vv * (1.0f + erff(vv * 0.70710678118654752f));
                    if (resid) vv += resid[(size_t)gr * N + gc];
                    Co[(size_t)gr * N + gc] = vv;
                }
            }
            __syncwarp();
        }
    }
}

// ---------------------------------------------------------------------------
static void launch_gemm(const float* A, const float* Bm, float* C,
                        const float* bias, const float* resid,
                        int M, int N, int K,
                        size_t sA, size_t sB, size_t sC, int batch,
                        float alpha, int transB, int gelu)
{
    dim3 grid((N + 127) / 128, (M + 127) / 128, batch);
    gemm_tf32<<<grid, 256>>>(A, Bm, C, bias, resid, M, N, K, sA, sB, sC, alpha, transB, gelu);
}

extern "C" void kernel_launch(void* const* d_in, const int* in_sizes, int n_in,
                              void* d_out, int out_size)
{
    const float* x     = (const float*)d_in[0];
    const float* rcos  = (const float*)d_in[1];
    const float* rsin  = (const float*)d_in[2];
    const float* ln1_g = (const float*)d_in[3];
    const float* ln1_b = (const float*)d_in[4];
    const float* Wq    = (const float*)d_in[5];
    const float* bq    = (const float*)d_in[6];
    const float* Wk    = (const float*)d_in[7];
    const float* bk    = (const float*)d_in[8];
    const float* Wv    = (const float*)d_in[9];
    const float* bv    = (const float*)d_in[10];
    const float* Wo    = (const float*)d_in[11];
    const float* bo    = (const float*)d_in[12];
    const float* ln2_g = (const float*)d_in[13];
    const float* ln2_b = (const float*)d_in[14];
    const float* W1    = (const float*)d_in[15];
    const float* b1    = (const float*)d_in[16];
    const float* W2    = (const float*)d_in[17];
    const float* b2    = (const float*)d_in[18];
    float* out = (float*)d_out;

    void* sp = nullptr;
    cudaGetSymbolAddress(&sp, g_scratch);
    float* base = (float*)sp;
    float* h   = base + OFF_H;
    float* ql  = base + OFF_QL;
    float* kl  = base + OFF_KL;
    float* vl  = base + OFF_VL;
    float* qr  = base + OFF_QR;
    float* kr  = base + OFF_KR;
    float* vt  = base + OFF_VT;
    float* S   = base + OFF_S;
    float* ao  = base + OFF_AO;
    float* aot = base + OFF_AOT;
    float* x1  = base + OFF_X1;
    float* h2  = base + OFF_H2;
    float* g1  = base + OFF_G1;

    // 1. LN1
    ln_kernel<<<MR, 256>>>(x, ln1_g, ln1_b, h);

    // 2. QKV projections (C = h * W^T + b)
    launch_gemm(h, Wq, ql, bq, nullptr, MR, Cc_, Cc_, 0, 0, 0, 1, 1.0f, 1, 0);
    launch_gemm(h, Wk, kl, bk, nullptr, MR, Cc_, Cc_, 0, 0, 0, 1, 1.0f, 1, 0);
    launch_gemm(h, Wv, vl, bv, nullptr, MR, Cc_, Cc_, 0, 0, 0, 1, 1.0f, 1, 0);

    // 3. RoPE + transpose to [B,H,N,D]
    {
        int total = Bb * Hh * Nn * Dd;
        rope_kernel<<<(total + 255) / 256, 256>>>(ql, kl, vl, rcos, rsin, qr, kr, vt);
    }

    // 4. Scores: S = (q k^T) * D^-0.5, batched over B*H
    launch_gemm(qr, kr, S, nullptr, nullptr, Nn, Nn, Dd,
                (size_t)Nn * Dd, (size_t)Nn * Dd, (size_t)Nn * Nn,
                Bb * Hh, 0.125f, 1, 0);

    // 5. Softmax rows
    softmax_kernel<<<Bb * Hh * Nn, 256>>>(S);

    // 6. O = P * V (B non-transposed), batched
    launch_gemm(S, vt, ao, nullptr, nullptr, Nn, Dd, Nn,
                (size_t)Nn * Nn, (size_t)Nn * Dd, (size_t)Nn * Dd,
                Bb * Hh, 1.0f, 0, 0);

    // 7. Back to [B,N,C]
    {
        int total = Bb * Nn * Cc_;
        unpermute_kernel<<<(total + 255) / 256, 256>>>(ao, aot);
    }

    // 8. O-proj + bias + residual(x) -> x1
    launch_gemm(aot, Wo, x1, bo, x, MR, Cc_, Cc_, 0, 0, 0, 1, 1.0f, 1, 0);

    // 9. LN2
    ln_kernel<<<MR, 256>>>(x1, ln2_g, ln2_b, h2);

    // 10. FFN1 + bias + exact GELU
    launch_gemm(h2, W1, g1, b1, nullptr, MR, Ff, Cc_, 0, 0, 0, 1, 1.0f, 1, 1);

    // 11. FFN2 + bias + residual(x1) -> out
    launch_gemm(g1, W2, out, b2, x1, MR, Cc_, Ff, 0, 0, 0, 1, 1.0f, 1, 0);
}

// round 8
// speedup vs baseline: 3.4572x; 3.4572x over previous
#include <cuda_runtime.h>
#include <cstdint>
#include <math.h>

// Problem dims
constexpr int  Bb = 2, Nn = 2048, Cc_ = 1024, Hh = 16, Dd = 64, Ff = 4096;
constexpr int  MR = Bb * Nn;                 // 4096 token rows
constexpr size_t SZ4M = (size_t)MR * Cc_;    // 4M floats

// Scratch layout (floats)
constexpr size_t OFF_H   = 0;
constexpr size_t OFF_QL  = OFF_H   + SZ4M;
constexpr size_t OFF_KL  = OFF_QL  + SZ4M;
constexpr size_t OFF_VL  = OFF_KL  + SZ4M;
constexpr size_t OFF_QR  = OFF_VL  + SZ4M;
constexpr size_t OFF_KR  = OFF_QR  + SZ4M;
constexpr size_t OFF_VT  = OFF_KR  + SZ4M;           // V transposed [B,H,D,N]
constexpr size_t OFF_S   = OFF_VT  + SZ4M;           // scores 32*2048*2048
constexpr size_t SZ_S    = (size_t)Bb * Hh * Nn * Nn;
constexpr size_t OFF_AO  = OFF_S   + SZ_S;
constexpr size_t OFF_AOT = OFF_AO  + SZ4M;
constexpr size_t OFF_X1  = OFF_AOT + SZ4M;
constexpr size_t OFF_H2  = OFF_X1  + SZ4M;
constexpr size_t OFF_G1  = OFF_H2  + SZ4M;
constexpr size_t SZ_G1   = (size_t)MR * Ff;
constexpr size_t SCRATCH_FLOATS = OFF_G1 + SZ_G1;

__device__ float g_scratch[SCRATCH_FLOATS];

// ---------------------------------------------------------------------------
// PTX helpers
// ---------------------------------------------------------------------------
__device__ __forceinline__ uint32_t f2tf32(float x) {
    uint32_t r;
    asm("cvt.rna.tf32.f32 %0, %1;" : "=r"(r) : "f"(x));
    return r;
}

__device__ __forceinline__ void mma_m16n8k8(float* c, const uint32_t* a, const uint32_t* b) {
    asm volatile(
        "mma.sync.aligned.m16n8k8.row.col.f32.tf32.tf32.f32 "
        "{%0,%1,%2,%3}, {%4,%5,%6,%7}, {%8,%9}, {%0,%1,%2,%3};"
        : "+f"(c[0]), "+f"(c[1]), "+f"(c[2]), "+f"(c[3])
        : "r"(a[0]), "r"(a[1]), "r"(a[2]), "r"(a[3]), "r"(b[0]), "r"(b[1]));
}

#define CP_ASYNC_CG(dst_u32, src_ptr) \
    asm volatile("cp.async.cg.shared.global [%0], [%1], 16;" :: "r"(dst_u32), "l"(src_ptr))
#define CP_COMMIT() asm volatile("cp.async.commit_group;")
#define CP_WAIT1()  asm volatile("cp.async.wait_group 1;")

// ---------------------------------------------------------------------------
// LayerNorm: one block per row (C=1024)
// ---------------------------------------------------------------------------
__global__ __launch_bounds__(256) void ln_kernel(const float* __restrict__ x,
                                                 const float* __restrict__ g,
                                                 const float* __restrict__ b,
                                                 float* __restrict__ out)
{
    const int row = blockIdx.x;
    const int t = threadIdx.x;
    const float* xr = x + (size_t)row * Cc_;

    float4 v = *reinterpret_cast<const float4*>(xr + t * 4);
    float s  = v.x + v.y + v.z + v.w;
    float ss = v.x * v.x + v.y * v.y + v.z * v.z + v.w * v.w;
    #pragma unroll
    for (int o = 16; o > 0; o >>= 1) {
        s  += __shfl_xor_sync(0xffffffff, s,  o);
        ss += __shfl_xor_sync(0xffffffff, ss, o);
    }
    __shared__ float red0[8], red1[8];
    int w = t >> 5;
    if ((t & 31) == 0) { red0[w] = s; red1[w] = ss; }
    __syncthreads();
    float st = 0.f, sst = 0.f;
    #pragma unroll
    for (int i = 0; i < 8; i++) { st += red0[i]; sst += red1[i]; }

    const float mean = st * (1.0f / Cc_);
    const float var  = sst * (1.0f / Cc_) - mean * mean;
    const float inv  = rsqrtf(var + 1e-6f);

    float4 gv = *reinterpret_cast<const float4*>(g + t * 4);
    float4 bv = *reinterpret_cast<const float4*>(b + t * 4);
    float4 o4;
    o4.x = (v.x - mean) * inv * gv.x + bv.x;
    o4.y = (v.y - mean) * inv * gv.y + bv.y;
    o4.z = (v.z - mean) * inv * gv.z + bv.z;
    o4.w = (v.w - mean) * inv * gv.w + bv.w;
    *reinterpret_cast<float4*>(out + (size_t)row * Cc_ + t * 4) = o4;
}

// ---------------------------------------------------------------------------
// RoPE + head transpose for q,k: [B,N,H,D] -> [B,H,N,D]
// ---------------------------------------------------------------------------
__global__ __launch_bounds__(256) void rope_kernel(const float* __restrict__ ql,
                                                   const float* __restrict__ kl,
                                                   const float* __restrict__ cosT,
                                                   const float* __restrict__ sinT,
                                                   float* __restrict__ qr,
                                                   float* __restrict__ kr)
{
    int idx = blockIdx.x * blockDim.x + threadIdx.x;   // over B*H*N*D = 4M
    if (idx >= Bb * Hh * Nn * Dd) return;
    const int d = idx & 63;
    const int n = (idx >> 6) & 2047;
    const int h = (idx >> 17) & 15;
    const int bidx = idx >> 21;
    const size_t inBase = ((size_t)(bidx * Nn + n)) * Cc_ + h * Dd;
    const float c = cosT[n * Dd + d];
    const float s = sinT[n * Dd + d];
    const float qv = ql[inBase + d];
    const float kv = kl[inBase + d];
    float qp, kp;
    if (d < 32) { qp = -ql[inBase + d + 32]; kp = -kl[inBase + d + 32]; }
    else        { qp =  ql[inBase + d - 32]; kp =  kl[inBase + d - 32]; }
    qr[idx] = qv * c + qp * s;
    kr[idx] = kv * c + kp * s;
}

// ---------------------------------------------------------------------------
// V transpose: [B,N,H*D] -> [B,H,D,N]  (tiled, coalesced both sides)
// grid (Nn/32, Hh, Bb), 256 threads
// ---------------------------------------------------------------------------
__global__ __launch_bounds__(256) void vtrans_kernel(const float* __restrict__ vl,
                                                     float* __restrict__ vt)
{
    __shared__ float s[32][65];
    const int nb = blockIdx.x * 32, h = blockIdx.y, b = blockIdx.z;
    const int tid = threadIdx.x;
    const int d = tid & 63, n4 = tid >> 6;
    #pragma unroll
    for (int it = 0; it < 8; it++) {
        int n = n4 + it * 4;
        s[n][d] = vl[((size_t)(b * Nn + nb + n)) * Cc_ + h * Dd + d];
    }
    __syncthreads();
    const int nn = tid & 31, d8 = tid >> 5;
    #pragma unroll
    for (int it = 0; it < 8; it++) {
        int dd = d8 + it * 8;
        vt[(((size_t)(b * Hh + h)) * Dd + dd) * Nn + nb + nn] = s[nn][dd];
    }
}

// ---------------------------------------------------------------------------
// Softmax over rows of length 2048
// ---------------------------------------------------------------------------
__global__ __launch_bounds__(256) void softmax_kernel(float* __restrict__ S)
{
    const size_t row = blockIdx.x;
    float* p = S + row * (size_t)Nn;
    const int t = threadIdx.x;

    float4 v0 = *reinterpret_cast<const float4*>(p + t * 4);
    float4 v1 = *reinterpret_cast<const float4*>(p + 1024 + t * 4);

    float m = fmaxf(fmaxf(fmaxf(v0.x, v0.y), fmaxf(v0.z, v0.w)),
                    fmaxf(fmaxf(v1.x, v1.y), fmaxf(v1.z, v1.w)));
    #pragma unroll
    for (int o = 16; o > 0; o >>= 1) m = fmaxf(m, __shfl_xor_sync(0xffffffff, m, o));
    __shared__ float red[8];
    int w = t >> 5;
    if ((t & 31) == 0) red[w] = m;
    __syncthreads();
    float mx = red[0];
    #pragma unroll
    for (int i = 1; i < 8; i++) mx = fmaxf(mx, red[i]);
    __syncthreads();

    v0.x = expf(v0.x - mx); v0.y = expf(v0.y - mx); v0.z = expf(v0.z - mx); v0.w = expf(v0.w - mx);
    v1.x = expf(v1.x - mx); v1.y = expf(v1.y - mx); v1.z = expf(v1.z - mx); v1.w = expf(v1.w - mx);
    float s = v0.x + v0.y + v0.z + v0.w + v1.x + v1.y + v1.z + v1.w;
    #pragma unroll
    for (int o = 16; o > 0; o >>= 1) s += __shfl_xor_sync(0xffffffff, s, o);
    if ((t & 31) == 0) red[w] = s;
    __syncthreads();
    float st = 0.f;
    #pragma unroll
    for (int i = 0; i < 8; i++) st += red[i];
    const float inv = 1.0f / st;

    v0.x *= inv; v0.y *= inv; v0.z *= inv; v0.w *= inv;
    v1.x *= inv; v1.y *= inv; v1.z *= inv; v1.w *= inv;
    *reinterpret_cast<float4*>(p + t * 4)        = v0;
    *reinterpret_cast<float4*>(p + 1024 + t * 4) = v1;
}

// ---------------------------------------------------------------------------
// [B,H,N,D] -> [B,N,H*D]
// ---------------------------------------------------------------------------
__global__ __launch_bounds__(256) void unpermute_kernel(const float* __restrict__ ao,
                                                        float* __restrict__ aot)
{
    int idx = blockIdx.x * blockDim.x + threadIdx.x;
    if (idx >= Bb * Nn * Cc_) return;
    const int c = idx & 1023;
    const int n = (idx >> 10) & 2047;
    const int bidx = idx >> 21;
    const int h = c >> 6;
    const int d = c & 63;
    aot[idx] = ao[(((size_t)(bidx * Hh + h) * Nn) + n) * Dd + d];
}

// ---------------------------------------------------------------------------
// tf32 mma GEMM:  C[M,N] = alpha * A[M,K] * B[N,K]^T  (+bias)(gelu)(+resid)
// BM=128, BK=32, STAGES=3 cp.async pipeline, XOR-swizzled smem (conflict-free),
// PTX m16n8k8, direct register epilogue. All dims must divide tiles (they do).
// ---------------------------------------------------------------------------
template<int BN>
__global__ __launch_bounds__(256) void gemm_mma(const float* __restrict__ A,
                                                const float* __restrict__ B,
                                                float* __restrict__ C,
                                                const float* __restrict__ bias,
                                                const float* __restrict__ resid,
                                                int M, int N, int K,
                                                size_t sA, size_t sB, size_t sC,
                                                float alpha, int gelu)
{
    constexpr int BM = 128, BK = 32, STAGES = 3;
    constexpr int WARPS_M = (BN == 128) ? 2 : 4;
    constexpr int WARPS_N = 8 / WARPS_M;
    constexpr int MT = BM / (16 * WARPS_M);   // 4 (BN=128) / 2 (BN=64)
    constexpr int NT = BN / (8 * WARPS_N);    // 4
    constexpr int ACH = BM * (BK / 4);        // float4 chunks per A stage
    constexpr int BCH = BN * (BK / 4);

    extern __shared__ float smem[];
    float* As = smem;                              // STAGES*BM*BK
    float* Bs = smem + STAGES * BM * BK;           // STAGES*BN*BK

    const int tid = threadIdx.x;
    const int wid = tid >> 5, lane = tid & 31;
    const int g = lane >> 2, tg = lane & 3;
    const int wm = wid % WARPS_M, wn = wid / WARPS_M;

    const int rowBase = blockIdx.y * BM;
    const int colBase = blockIdx.x * BN;
    const int bz = blockIdx.z;
    A += (size_t)bz * sA + (size_t)rowBase * K;
    B += (size_t)bz * sB + (size_t)colBase * K;
    C += (size_t)bz * sC;

    const uint32_t sAu = (uint32_t)__cvta_generic_to_shared(As);
    const uint32_t sBu = (uint32_t)__cvta_generic_to_shared(Bs);

    float acc[MT][NT][4];
    #pragma unroll
    for (int i = 0; i < MT; i++)
        #pragma unroll
        for (int j = 0; j < NT; j++)
            #pragma unroll
            for (int e = 0; e < 4; e++) acc[i][j][e] = 0.f;

    auto load_stage = [&](int kt, int stage) {
        const float* Ap = A + kt * BK;
        const float* Bp = B + kt * BK;
        const uint32_t sa = sAu + (uint32_t)(stage * BM * BK * 4);
        const uint32_t sb = sBu + (uint32_t)(stage * BN * BK * 4);
        #pragma unroll
        for (int i = 0; i < ACH / 256; i++) {
            int v = tid + i * 256;
            int r = v >> 3, c4 = v & 7;
            uint32_t dst = sa + (uint32_t)((r * 8 + (c4 ^ (r & 7))) * 16);
            CP_ASYNC_CG(dst, Ap + (size_t)r * K + c4 * 4);
        }
        #pragma unroll
        for (int i = 0; i < BCH / 256; i++) {
            int v = tid + i * 256;
            int r = v >> 3, c4 = v & 7;
            uint32_t dst = sb + (uint32_t)((r * 8 + (c4 ^ (r & 7))) * 16);
            CP_ASYNC_CG(dst, Bp + (size_t)r * K + c4 * 4);
        }
    };

    auto compute_stage = [&](int stage) {
        const float* as = As + stage * BM * BK;
        const float* bs = Bs + stage * BN * BK;
        #pragma unroll
        for (int ks = 0; ks < BK / 8; ks++) {
            const int off0 = (((2 * ks)     ^ g) << 2) + tg;
            const int off1 = (((2 * ks + 1) ^ g) << 2) + tg;
            uint32_t af[MT][4], bf[NT][2];
            #pragma unroll
            for (int i = 0; i < MT; i++) {
                const float* ap = as + (wm * MT * 16 + i * 16 + g) * 32;
                af[i][0] = f2tf32(ap[off0]);
                af[i][1] = f2tf32(ap[8 * 32 + off0]);
                af[i][2] = f2tf32(ap[off1]);
                af[i][3] = f2tf32(ap[8 * 32 + off1]);
            }
            #pragma unroll
            for (int j = 0; j < NT; j++) {
                const float* bp = bs + (wn * NT * 8 + j * 8 + g) * 32;
                bf[j][0] = f2tf32(bp[off0]);
                bf[j][1] = f2tf32(bp[off1]);
            }
            #pragma unroll
            for (int i = 0; i < MT; i++)
                #pragma unroll
                for (int j = 0; j < NT; j++)
                    mma_m16n8k8(acc[i][j], af[i], bf[j]);
        }
    };

    const int kTiles = K >> 5;

    #pragma unroll
    for (int s = 0; s < STAGES - 1; s++) {
        if (s < kTiles) load_stage(s, s);
        CP_COMMIT();
    }

    for (int kt = 0; kt < kTiles; kt++) {
        CP_WAIT1();
        __syncthreads();
        int nxt = kt + STAGES - 1;
        if (nxt < kTiles) load_stage(nxt, nxt % STAGES);
        CP_COMMIT();
        compute_stage(kt % STAGES);
    }

    // Direct epilogue from accumulator registers.
    #pragma unroll
    for (int i = 0; i < MT; i++) {
        const int r0 = rowBase + wm * MT * 16 + i * 16 + g;
        const int r1 = r0 + 8;
        #pragma unroll
        for (int j = 0; j < NT; j++) {
            const int c0 = colBase + wn * NT * 8 + j * 8 + tg * 2;
            float v00 = acc[i][j][0] * alpha;
            float v01 = acc[i][j][1] * alpha;
            float v10 = acc[i][j][2] * alpha;
            float v11 = acc[i][j][3] * alpha;
            if (bias) {
                float bx = __ldg(bias + c0), by = __ldg(bias + c0 + 1);
                v00 += bx; v01 += by; v10 += bx; v11 += by;
            }
            if (gelu) {
                v00 = 0.5f * v00 * (1.0f + erff(v00 * 0.70710678118654752f));
                v01 = 0.5f * v01 * (1.0f + erff(v01 * 0.70710678118654752f));
                v10 = 0.5f * v10 * (1.0f + erff(v10 * 0.70710678118654752f));
                v11 = 0.5f * v11 * (1.0f + erff(v11 * 0.70710678118654752f));
            }
            if (resid) {
                const float2 r0v = *reinterpret_cast<const float2*>(resid + (size_t)r0 * N + c0);
                const float2 r1v = *reinterpret_cast<const float2*>(resid + (size_t)r1 * N + c0);
                v00 += r0v.x; v01 += r0v.y; v10 += r1v.x; v11 += r1v.y;
            }
            *reinterpret_cast<float2*>(C + (size_t)r0 * N + c0) = make_float2(v00, v01);
            *reinterpret_cast<float2*>(C + (size_t)r1 * N + c0) = make_float2(v10, v11);
        }
    }
}

// ---------------------------------------------------------------------------
constexpr int SMEM128 = 3 * (128 + 128) * 32 * 4;  // 98304
constexpr int SMEM64  = 3 * (128 + 64)  * 32 * 4;  // 73728

static void g128(const float* A, const float* B, float* C,
                 const float* bias, const float* resid,
                 int M, int N, int K,
                 size_t sA, size_t sB, size_t sC, int batch,
                 float alpha, int gelu)
{
    dim3 grid(N / 128, M / 128, batch);
    gemm_mma<128><<<grid, 256, SMEM128>>>(A, B, C, bias, resid, M, N, K, sA, sB, sC, alpha, gelu);
}

static void g64(const float* A, const float* B, float* C,
                int M, int N, int K,
                size_t sA, size_t sB, size_t sC, int batch)
{
    dim3 grid(N / 64, M / 128, batch);
    gemm_mma<64><<<grid, 256, SMEM64>>>(A, B, C, nullptr, nullptr, M, N, K, sA, sB, sC, 1.0f, 0);
}

extern "C" void kernel_launch(void* const* d_in, const int* in_sizes, int n_in,
                              void* d_out, int out_size)
{
    const float* x     = (const float*)d_in[0];
    const float* rcos  = (const float*)d_in[1];
    const float* rsin  = (const float*)d_in[2];
    const float* ln1_g = (const float*)d_in[3];
    const float* ln1_b = (const float*)d_in[4];
    const float* Wq    = (const float*)d_in[5];
    const float* bq    = (const float*)d_in[6];
    const float* Wk    = (const float*)d_in[7];
    const float* bk    = (const float*)d_in[8];
    const float* Wv    = (const float*)d_in[9];
    const float* bv    = (const float*)d_in[10];
    const float* Wo    = (const float*)d_in[11];
    const float* bo    = (const float*)d_in[12];
    const float* ln2_g = (const float*)d_in[13];
    const float* ln2_b = (const float*)d_in[14];
    const float* W1    = (const float*)d_in[15];
    const float* b1    = (const float*)d_in[16];
    const float* W2    = (const float*)d_in[17];
    const float* b2    = (const float*)d_in[18];
    float* out = (float*)d_out;

    // Opt into >48KB dynamic smem (idempotent, capture-transparent).
    cudaFuncSetAttribute(gemm_mma<128>, cudaFuncAttributeMaxDynamicSharedMemorySize, SMEM128);
    cudaFuncSetAttribute(gemm_mma<64>,  cudaFuncAttributeMaxDynamicSharedMemorySize, SMEM64);

    void* sp = nullptr;
    cudaGetSymbolAddress(&sp, g_scratch);
    float* base = (float*)sp;
    float* h   = base + OFF_H;
    float* ql  = base + OFF_QL;
    float* kl  = base + OFF_KL;
    float* vl  = base + OFF_VL;
    float* qr  = base + OFF_QR;
    float* kr  = base + OFF_KR;
    float* vt  = base + OFF_VT;
    float* S   = base + OFF_S;
    float* ao  = base + OFF_AO;
    float* aot = base + OFF_AOT;
    float* x1  = base + OFF_X1;
    float* h2  = base + OFF_H2;
    float* g1  = base + OFF_G1;

    // 1. LN1
    ln_kernel<<<MR, 256>>>(x, ln1_g, ln1_b, h);

    // 2. QKV projections
    g128(h, Wq, ql, bq, nullptr, MR, Cc_, Cc_, 0, 0, 0, 1, 1.0f, 0);
    g128(h, Wk, kl, bk, nullptr, MR, Cc_, Cc_, 0, 0, 0, 1, 1.0f, 0);
    g128(h, Wv, vl, bv, nullptr, MR, Cc_, Cc_, 0, 0, 0, 1, 1.0f, 0);

    // 3. RoPE (q,k) + V transpose to [B,H,D,N]
    {
        int total = Bb * Hh * Nn * Dd;
        rope_kernel<<<(total + 255) / 256, 256>>>(ql, kl, rcos, rsin, qr, kr);
        dim3 tg(Nn / 32, Hh, Bb);
        vtrans_kernel<<<tg, 256>>>(vl, vt);
    }

    // 4. Scores: S = (q k^T) * D^-0.5, batched over B*H
    g128(qr, kr, S, nullptr, nullptr, Nn, Nn, Dd,
         (size_t)Nn * Dd, (size_t)Nn * Dd, (size_t)Nn * Nn, Bb * Hh, 0.125f, 0);

    // 5. Softmax rows
    softmax_kernel<<<Bb * Hh * Nn, 256>>>(S);

    // 6. O = P * V  : A=S[2048,2048], B=Vt[64,2048] (K-contiguous), C=ao[2048,64]
    g64(S, vt, ao, Nn, Dd, Nn,
        (size_t)Nn * Nn, (size_t)Dd * Nn, (size_t)Nn * Dd, Bb * Hh);

    // 7. [B,H,N,D] -> [B,N,C]
    {
        int total = Bb * Nn * Cc_;
        unpermute_kernel<<<(total + 255) / 256, 256>>>(ao, aot);
    }

    // 8. O-proj + bias + residual(x)
    g128(aot, Wo, x1, bo, x, MR, Cc_, Cc_, 0, 0, 0, 1, 1.0f, 0);

    // 9. LN2
    ln_kernel<<<MR, 256>>>(x1, ln2_g, ln2_b, h2);

    // 10. FFN1 + bias + exact GELU
    g128(h2, W1, g1, b1, nullptr, MR, Ff, Cc_, 0, 0, 0, 1, 1.0f, 1);

    // 11. FFN2 + bias + residual(x1)
    g128(g1, W2, out, b2, x1, MR, Cc_, Ff, 0, 0, 0, 1, 1.0f, 0);
}